// round 7
// baseline (speedup 1.0000x reference)
#include <cuda_runtime.h>
#include <cstdint>

#define DIM   64
#define ODIM  16
#define NMAX  100000
#define EMAX  1600000
#define GMAX  512

// ---- scratch (no allocations allowed; __device__ globals per rules) ----
// INVARIANT: d_deg is all-zero at kernel_launch entry (zero at module load;
// scan_k re-zeroes after reading, so every replay restores the invariant).
__device__ __align__(16) float d_agg[(size_t)NMAX * DIM];
__device__ __align__(16) float d_h1 [(size_t)NMAX * DIM];
__device__ __align__(16) float d_pool[(size_t)GMAX * DIM];
__device__ float d_gcnt[GMAX];
__device__ int d_deg[NMAX];
__device__ int d_off[NMAX + 1];
__device__ int d_cur[NMAX];
__device__ int d_col[EMAX];

// ---- helpers ----
__device__ __forceinline__ void red_add_v4(float* p, float4 v) {
    asm volatile("red.global.add.v4.f32 [%0], {%1,%2,%3,%4};"
                 :: "l"(p), "f"(v.x), "f"(v.y), "f"(v.z), "f"(v.w) : "memory");
}
__device__ __forceinline__ unsigned long long pack2(float v) {
    unsigned long long r;
    asm("mov.b64 %0, {%1,%1};" : "=l"(r) : "r"(__float_as_uint(v)));
    return r;
}
__device__ __forceinline__ void unpack2(unsigned long long v, float& lo, float& hi) {
    unsigned int a, b;
    asm("mov.b64 {%0,%1}, %2;" : "=r"(a), "=r"(b) : "l"(v));
    lo = __uint_as_float(a); hi = __uint_as_float(b);
}
#define FMA2(acc, a, b) \
    asm("fma.rn.f32x2 %0, %1, %2, %0;" : "+l"(acc) : "l"(a), "l"(b))

// ---- launch 1: degree count + (piggyback) pool zero + group counts ----
__global__ void count_k(const int* __restrict__ ei, int E,
                        const int* __restrict__ batch, int n, int G) {
    int b = blockIdx.x;
    int tid = threadIdx.x;
    int e = b * 256 + tid;
    if (e < E) atomicAdd(&d_deg[__ldg(&ei[E + e])], 1);
    if (b < 128) {                       // zero pool (512*64 = 32768 floats)
        int i = b * 256 + tid;
        if (i < G * DIM) d_pool[i] = 0.f;
    } else if (b < 130) {                // group counts via binary search (batch sorted)
        int g = (b - 128) * 256 + tid;
        if (g < G) {
            int lo = 0, hi = n;
            while (lo < hi) { int m = (lo + hi) >> 1; if (batch[m] < g) lo = m + 1; else hi = m; }
            int lo2 = lo, hi2 = n;
            while (lo2 < hi2) { int m = (lo2 + hi2) >> 1; if (batch[m] < g + 1) lo2 = m + 1; else hi2 = m; }
            d_gcnt[g] = (float)(lo2 - lo);
        }
    }
}

// ---- launch 2: single-block exclusive scan deg -> off/cur; re-zero deg ----
__global__ __launch_bounds__(1024)
void scan_k(int n, int E) {
    __shared__ int wsum[32];
    __shared__ int carry;
    int tid = threadIdx.x, lane = tid & 31, w = tid >> 5;
    if (tid == 0) carry = 0;
    __syncthreads();
    for (int base = 0; base < n; base += 1024) {
        int i = base + tid;
        int v = 0;
        if (i < n) { v = d_deg[i]; d_deg[i] = 0; }   // read + restore zero invariant
        int s = v;
#pragma unroll
        for (int o = 1; o < 32; o <<= 1) {
            int t = __shfl_up_sync(0xffffffffu, s, o);
            if (lane >= o) s += t;
        }
        if (lane == 31) wsum[w] = s;
        __syncthreads();                              // sync1
        if (w == 0) {
            int ws = wsum[lane];
#pragma unroll
            for (int o = 1; o < 32; o <<= 1) {
                int t = __shfl_up_sync(0xffffffffu, ws, o);
                if (lane >= o) ws += t;
            }
            wsum[lane] = ws;
        }
        __syncthreads();                              // sync2
        int prefix = carry + (w ? wsum[w - 1] : 0);
        int excl = prefix + s - v;
        if (i < n) { d_off[i] = excl; d_cur[i] = excl; }
        int total = wsum[31];                         // snapshot before sync3
        __syncthreads();                              // sync3 (carry read done)
        if (tid == 0) carry += total;
    }
    if (tid == 0) d_off[n] = E;
}

// ---- launch 3: CSR fill ----
__global__ void fill_k(const int* __restrict__ ei, int E) {
    int e = blockIdx.x * blockDim.x + threadIdx.x;
    if (e >= E) return;
    int s = __ldg(&ei[e]);
    int d = __ldg(&ei[E + e]);
    int p = atomicAdd(&d_cur[d], 1);
    d_col[p] = s;
}

// ---- gather: warp per node; indices batch-loaded coalesced, shfl-broadcast ----
__global__ __launch_bounds__(256)
void gather_k(const float* __restrict__ feat, float* __restrict__ agg, int N) {
    int node = (blockIdx.x * 256 + threadIdx.x) >> 5;
    int lane = threadIdx.x & 31;
    if (node >= N) return;
    int beg = d_off[node];
    int end = d_off[node + 1];
    int half = lane >> 4;
    int col4 = lane & 15;
    const float4* f4 = (const float4*)feat;
    float4 acc = make_float4(0.f, 0.f, 0.f, 0.f);
    for (int b = beg; b < end; b += 32) {
        int m = min(32, end - b);
        int idx = (lane < m) ? __ldg(&d_col[b + lane]) : 0;
        int j = 0;
        for (; j + 8 <= m; j += 8) {
            int c0 = __shfl_sync(0xffffffffu, idx, j     + half);
            int c1 = __shfl_sync(0xffffffffu, idx, j + 2 + half);
            int c2 = __shfl_sync(0xffffffffu, idx, j + 4 + half);
            int c3 = __shfl_sync(0xffffffffu, idx, j + 6 + half);
            float4 v0 = __ldg(f4 + (size_t)c0 * 16 + col4);
            float4 v1 = __ldg(f4 + (size_t)c1 * 16 + col4);
            float4 v2 = __ldg(f4 + (size_t)c2 * 16 + col4);
            float4 v3 = __ldg(f4 + (size_t)c3 * 16 + col4);
            acc.x += (v0.x + v1.x) + (v2.x + v3.x);
            acc.y += (v0.y + v1.y) + (v2.y + v3.y);
            acc.z += (v0.z + v1.z) + (v2.z + v3.z);
            acc.w += (v0.w + v1.w) + (v2.w + v3.w);
        }
        for (; j + 2 <= m; j += 2) {
            int c = __shfl_sync(0xffffffffu, idx, j + half);
            float4 v = __ldg(f4 + (size_t)c * 16 + col4);
            acc.x += v.x; acc.y += v.y; acc.z += v.z; acc.w += v.w;
        }
        if (j < m) {
            int c = __shfl_sync(0xffffffffu, idx, m - 1);
            if (half == 0) {
                float4 v = __ldg(f4 + (size_t)c * 16 + col4);
                acc.x += v.x; acc.y += v.y; acc.z += v.z; acc.w += v.w;
            }
        }
    }
    acc.x += __shfl_xor_sync(0xffffffffu, acc.x, 16);
    acc.y += __shfl_xor_sync(0xffffffffu, acc.y, 16);
    acc.z += __shfl_xor_sync(0xffffffffu, acc.z, 16);
    acc.w += __shfl_xor_sync(0xffffffffu, acc.w, 16);
    if (half == 0) {
        float inv = 1.f / (float)max(end - beg, 1);
        acc.x *= inv; acc.y *= inv; acc.z *= inv; acc.w *= inv;
        *(float4*)(agg + (size_t)node * DIM + col4 * 4) = acc;
    }
}

// ---- fused SAGE node update, 2-node register tiling, rotated weight layout ----
__global__ __launch_bounds__(256)
void node_k(const float* __restrict__ xin, const float* __restrict__ agg,
            const float* __restrict__ Wl, const float* __restrict__ bl,
            const float* __restrict__ Wr, float* __restrict__ hout,
            const int* __restrict__ batch, int n_nodes) {
    __shared__ __align__(16) float wlT[DIM * DIM];
    __shared__ __align__(16) float wrT[DIM * DIM];
    __shared__ __align__(16) float ash[32 * DIM];
    __shared__ __align__(16) float xsh[32 * DIM];

    int tid = threadIdx.x;
    for (int i = tid; i < DIM * DIM; i += 256) {
        int o = i >> 6, k = i & 63;
        int rot = (o + 4 * k) & 63;
        wlT[k * DIM + rot] = Wl[i];
        wrT[k * DIM + rot] = Wr[i];
    }
    int q = tid & 15;
    int s = tid >> 4;
    float4 bq = *(const float4*)(bl + 4 * q);

    const float4* agg4 = (const float4*)agg;
    const float4* x4   = (const float4*)xin;
    int base = blockIdx.x * 128;

    for (int r = 0; r < 4; r++) {
        int nb = base + r * 32;
        __syncthreads();
        {
            long long g0 = (long long)nb * 16 + tid;
            long long g1 = g0 + 256;
            long long lim = (long long)n_nodes * 16;
            float4 z = make_float4(0.f, 0.f, 0.f, 0.f);
            ((float4*)ash)[tid]       = (g0 < lim) ? agg4[g0] : z;
            ((float4*)xsh)[tid]       = (g0 < lim) ? x4[g0]   : z;
            ((float4*)ash)[tid + 256] = (g1 < lim) ? agg4[g1] : z;
            ((float4*)xsh)[tid + 256] = (g1 < lim) ? x4[g1]   : z;
        }
        __syncthreads();

        int n0 = nb + s, n1 = nb + s + 16;
        const float* ap0 = &ash[s * DIM];
        const float* xp0 = &xsh[s * DIM];
        const float* ap1 = &ash[(s + 16) * DIM];
        const float* xp1 = &xsh[(s + 16) * DIM];
        unsigned long long a0l0 = 0, a0l1 = 0, a0r0 = 0, a0r1 = 0;
        unsigned long long a1l0 = 0, a1l1 = 0, a1r0 = 0, a1r1 = 0;
#pragma unroll
        for (int k = 0; k < DIM; k++) {
            int rot = (4 * q + 4 * k) & 63;
            unsigned long long av0 = pack2(ap0[k]);
            unsigned long long xv0 = pack2(xp0[k]);
            unsigned long long av1 = pack2(ap1[k]);
            unsigned long long xv1 = pack2(xp1[k]);
            double2 wl = *(const double2*)&wlT[k * DIM + rot];
            double2 wr = *(const double2*)&wrT[k * DIM + rot];
            FMA2(a0l0, av0, __double_as_longlong(wl.x));
            FMA2(a0l1, av0, __double_as_longlong(wl.y));
            FMA2(a0r0, xv0, __double_as_longlong(wr.x));
            FMA2(a0r1, xv0, __double_as_longlong(wr.y));
            FMA2(a1l0, av1, __double_as_longlong(wl.x));
            FMA2(a1l1, av1, __double_as_longlong(wl.y));
            FMA2(a1r0, xv1, __double_as_longlong(wr.x));
            FMA2(a1r1, xv1, __double_as_longlong(wr.y));
        }
#pragma unroll
        for (int nn = 0; nn < 2; nn++) {
            int node = nn ? n1 : n0;
            if (node >= n_nodes) continue;
            float l0, l1, l2, l3, r0, r1, r2, r3;
            if (nn == 0) {
                unpack2(a0l0, l0, l1); unpack2(a0l1, l2, l3);
                unpack2(a0r0, r0, r1); unpack2(a0r1, r2, r3);
            } else {
                unpack2(a1l0, l0, l1); unpack2(a1l1, l2, l3);
                unpack2(a1r0, r0, r1); unpack2(a1r1, r2, r3);
            }
            float4 res;
            res.x = fmaxf(l0 + r0 + bq.x, 0.f);
            res.y = fmaxf(l1 + r1 + bq.y, 0.f);
            res.z = fmaxf(l2 + r2 + bq.z, 0.f);
            res.w = fmaxf(l3 + r3 + bq.w, 0.f);
            if (batch) {
                int g = batch[node];
                red_add_v4(&d_pool[(size_t)g * DIM + 4 * q], res);
            } else {
                *(float4*)&hout[(size_t)node * DIM + 4 * q] = res;
            }
        }
    }
}

// ---- pooled mean -> fc -> log_softmax ----
__global__ void final_k(const float* __restrict__ fcW, const float* __restrict__ fcb,
                        float* __restrict__ out, int G) {
    int g = blockIdx.x * blockDim.x + threadIdx.x;
    if (g >= G) return;
    float inv = 1.f / fmaxf(d_gcnt[g], 1.f);
    float p[DIM];
    const float* pr = &d_pool[(size_t)g * DIM];
#pragma unroll
    for (int k = 0; k < DIM; k++) p[k] = pr[k] * inv;
    float lg[ODIM];
#pragma unroll
    for (int o = 0; o < ODIM; o++) {
        float s = fcb[o];
        const float* w = &fcW[o * DIM];
#pragma unroll
        for (int k = 0; k < DIM; k++) s = fmaf(p[k], w[k], s);
        lg[o] = s;
    }
    float m = lg[0];
#pragma unroll
    for (int o = 1; o < ODIM; o++) m = fmaxf(m, lg[o]);
    float se = 0.f;
#pragma unroll
    for (int o = 0; o < ODIM; o++) se += expf(lg[o] - m);
    float lse = m + logf(se);
#pragma unroll
    for (int o = 0; o < ODIM; o++) out[g * ODIM + o] = lg[o] - lse;
}

extern "C" void kernel_launch(void* const* d_in, const int* in_sizes, int n_in,
                              void* d_out, int out_size) {
    const float* x   = (const float*)d_in[0];
    const float* W1l = (const float*)d_in[1];
    const float* b1  = (const float*)d_in[2];
    const float* W1r = (const float*)d_in[3];
    const float* W2l = (const float*)d_in[4];
    const float* b2  = (const float*)d_in[5];
    const float* W2r = (const float*)d_in[6];
    const float* fcW = (const float*)d_in[7];
    const float* fcb = (const float*)d_in[8];
    const int* ei    = (const int*)d_in[9];     // int32 (JAX x64 disabled)
    const int* batch = (const int*)d_in[10];

    int N = in_sizes[10];
    int E = in_sizes[9] / 2;
    int G = out_size / ODIM;

    float *agg, *h1;
    cudaGetSymbolAddress((void**)&agg, d_agg);
    cudaGetSymbolAddress((void**)&h1,  d_h1);

    // CSR build; d_deg zero-invariant carried across replays (restored by scan_k)
    count_k<<<(E + 255) / 256, 256>>>(ei, E, batch, N, G);   // 1 (+pool zero, +gcnt)
    scan_k<<<1, 1024>>>(N, E);                               // 2
    fill_k<<<(E + 255) / 256, 256>>>(ei, E);                 // 3

    // layer 1
    gather_k<<<(N + 7) / 8, 256>>>(x, agg, N);               // 4 <- profiled
    node_k<<<(N + 127) / 128, 256>>>(x, agg, W1l, b1, W1r, h1, nullptr, N);

    // layer 2
    gather_k<<<(N + 7) / 8, 256>>>(h1, agg, N);
    node_k<<<(N + 127) / 128, 256>>>(h1, agg, W2l, b2, W2r, nullptr, batch, N);

    // pool -> fc -> log_softmax
    final_k<<<(G + 255) / 256, 256>>>(fcW, fcb, (float*)d_out, G);
}

// round 8
// speedup vs baseline: 1.2090x; 1.2090x over previous
#include <cuda_runtime.h>
#include <cstdint>

#define DIM   64
#define ODIM  16
#define NMAX  100000
#define EMAX  1600000
#define GMAX  512
#define NB_SCAN 512

// ---- scratch (no allocations allowed; __device__ globals per rules) ----
// INVARIANT: d_deg all-zero at kernel_launch entry (zero at module load;
// scan1_k re-zeroes after reading, so every replay restores the invariant).
__device__ __align__(16) float d_agg[(size_t)NMAX * DIM];
__device__ __align__(16) float d_h1 [(size_t)NMAX * DIM];
__device__ __align__(16) float d_pool[(size_t)GMAX * DIM];
__device__ float d_gcnt[GMAX];
__device__ int d_deg[NMAX];
__device__ int d_off[NMAX + 1];
__device__ int d_cur[NMAX];
__device__ int d_col[EMAX];
__device__ int d_bsum[NB_SCAN];

// ---- helpers ----
__device__ __forceinline__ void red_add_v4(float* p, float4 v) {
    asm volatile("red.global.add.v4.f32 [%0], {%1,%2,%3,%4};"
                 :: "l"(p), "f"(v.x), "f"(v.y), "f"(v.z), "f"(v.w) : "memory");
}
__device__ __forceinline__ unsigned long long pack2(float v) {
    unsigned long long r;
    asm("mov.b64 %0, {%1,%1};" : "=l"(r) : "r"(__float_as_uint(v)));
    return r;
}
__device__ __forceinline__ void unpack2(unsigned long long v, float& lo, float& hi) {
    unsigned int a, b;
    asm("mov.b64 {%0,%1}, %2;" : "=r"(a), "=r"(b) : "l"(v));
    lo = __uint_as_float(a); hi = __uint_as_float(b);
}
#define FMA2(acc, a, b) \
    asm("fma.rn.f32x2 %0, %1, %2, %0;" : "+l"(acc) : "l"(a), "l"(b))

// ---- launch 1: degree count + (piggyback) pool zero + group counts ----
__global__ void count_k(const int* __restrict__ ei, int E,
                        const int* __restrict__ batch, int n, int G) {
    int b = blockIdx.x;
    int tid = threadIdx.x;
    int e = b * 256 + tid;
    if (e < E) atomicAdd(&d_deg[__ldg(&ei[E + e])], 1);
    if (b < 128) {                       // zero pool (512*64 = 32768 floats)
        int i = b * 256 + tid;
        if (i < G * DIM) d_pool[i] = 0.f;
    } else if (b < 130) {                // group counts via binary search (batch sorted)
        int g = (b - 128) * 256 + tid;
        if (g < G) {
            int lo = 0, hi = n;
            while (lo < hi) { int m = (lo + hi) >> 1; if (batch[m] < g) lo = m + 1; else hi = m; }
            int lo2 = lo, hi2 = n;
            while (lo2 < hi2) { int m = (lo2 + hi2) >> 1; if (batch[m] < g + 1) lo2 = m + 1; else hi2 = m; }
            d_gcnt[g] = (float)(lo2 - lo);
        }
    }
}

// ---- launch 2: per-block exclusive scan; re-zero deg (replay invariant) ----
__global__ void scan1_k(int n) {
    __shared__ int sh[256];
    int tid = threadIdx.x;
    int i = blockIdx.x * 256 + tid;
    int v = 0;
    if (i < n) { v = d_deg[i]; d_deg[i] = 0; }
    sh[tid] = v;
    __syncthreads();
#pragma unroll
    for (int o = 1; o < 256; o <<= 1) {
        int t = (tid >= o) ? sh[tid - o] : 0;
        __syncthreads();
        if (tid >= o) sh[tid] += t;
        __syncthreads();
    }
    if (i < n) d_off[i] = sh[tid] - v;
    if (tid == 255) d_bsum[blockIdx.x] = sh[255];
}
// ---- launch 3: fused level-2+3: block prefix of bsum, finalize offsets+cursors ----
__global__ void scan23_k(int n, int E) {
    __shared__ int red[8];
    __shared__ int sprev;
    int b = blockIdx.x;
    int tid = threadIdx.x;
    int s = 0;
    for (int j = tid; j < b; j += 256) s += d_bsum[j];
#pragma unroll
    for (int o = 16; o; o >>= 1) s += __shfl_xor_sync(0xffffffffu, s, o);
    if ((tid & 31) == 0) red[tid >> 5] = s;
    __syncthreads();
    if (tid == 0) {
        int t = 0;
#pragma unroll
        for (int w = 0; w < 8; w++) t += red[w];
        sprev = t;
    }
    __syncthreads();
    int i = b * 256 + tid;
    if (i < n) {
        int o = d_off[i] + sprev;
        d_off[i] = o;
        d_cur[i] = o;
    }
    if (b == 0 && tid == 0) d_off[n] = E;
}

// ---- launch 4 (profiled): CSR fill ----
__global__ void fill_k(const int* __restrict__ ei, int E) {
    int e = blockIdx.x * blockDim.x + threadIdx.x;
    if (e >= E) return;
    int s = __ldg(&ei[e]);
    int d = __ldg(&ei[E + e]);
    int p = atomicAdd(&d_cur[d], 1);
    d_col[p] = s;
}

// ---- gather: warp per node; idx batch-loaded coalesced + shfl-broadcast.
//      16-edge main batch = 8 independent LDG.128 in flight per thread. ----
__global__ __launch_bounds__(256)
void gather_k(const float* __restrict__ feat, float* __restrict__ agg, int N) {
    int node = (blockIdx.x * 256 + threadIdx.x) >> 5;
    int lane = threadIdx.x & 31;
    if (node >= N) return;
    int beg = d_off[node];
    int end = d_off[node + 1];
    int half = lane >> 4;
    int col4 = lane & 15;
    const float4* f4 = (const float4*)feat;
    float4 acc = make_float4(0.f, 0.f, 0.f, 0.f);
    for (int b = beg; b < end; b += 32) {
        int m = min(32, end - b);
        int idx = (lane < m) ? __ldg(&d_col[b + lane]) : 0;
        int j = 0;
        for (; j + 16 <= m; j += 16) {   // 16 edges: 8 LDG.128 in flight/thread
            int c0 = __shfl_sync(0xffffffffu, idx, j      + half);
            int c1 = __shfl_sync(0xffffffffu, idx, j +  2 + half);
            int c2 = __shfl_sync(0xffffffffu, idx, j +  4 + half);
            int c3 = __shfl_sync(0xffffffffu, idx, j +  6 + half);
            int c4 = __shfl_sync(0xffffffffu, idx, j +  8 + half);
            int c5 = __shfl_sync(0xffffffffu, idx, j + 10 + half);
            int c6 = __shfl_sync(0xffffffffu, idx, j + 12 + half);
            int c7 = __shfl_sync(0xffffffffu, idx, j + 14 + half);
            float4 v0 = __ldg(f4 + (size_t)c0 * 16 + col4);
            float4 v1 = __ldg(f4 + (size_t)c1 * 16 + col4);
            float4 v2 = __ldg(f4 + (size_t)c2 * 16 + col4);
            float4 v3 = __ldg(f4 + (size_t)c3 * 16 + col4);
            float4 v4 = __ldg(f4 + (size_t)c4 * 16 + col4);
            float4 v5 = __ldg(f4 + (size_t)c5 * 16 + col4);
            float4 v6 = __ldg(f4 + (size_t)c6 * 16 + col4);
            float4 v7 = __ldg(f4 + (size_t)c7 * 16 + col4);
            acc.x += ((v0.x + v1.x) + (v2.x + v3.x)) + ((v4.x + v5.x) + (v6.x + v7.x));
            acc.y += ((v0.y + v1.y) + (v2.y + v3.y)) + ((v4.y + v5.y) + (v6.y + v7.y));
            acc.z += ((v0.z + v1.z) + (v2.z + v3.z)) + ((v4.z + v5.z) + (v6.z + v7.z));
            acc.w += ((v0.w + v1.w) + (v2.w + v3.w)) + ((v4.w + v5.w) + (v6.w + v7.w));
        }
        for (; j + 8 <= m; j += 8) {
            int c0 = __shfl_sync(0xffffffffu, idx, j     + half);
            int c1 = __shfl_sync(0xffffffffu, idx, j + 2 + half);
            int c2 = __shfl_sync(0xffffffffu, idx, j + 4 + half);
            int c3 = __shfl_sync(0xffffffffu, idx, j + 6 + half);
            float4 v0 = __ldg(f4 + (size_t)c0 * 16 + col4);
            float4 v1 = __ldg(f4 + (size_t)c1 * 16 + col4);
            float4 v2 = __ldg(f4 + (size_t)c2 * 16 + col4);
            float4 v3 = __ldg(f4 + (size_t)c3 * 16 + col4);
            acc.x += (v0.x + v1.x) + (v2.x + v3.x);
            acc.y += (v0.y + v1.y) + (v2.y + v3.y);
            acc.z += (v0.z + v1.z) + (v2.z + v3.z);
            acc.w += (v0.w + v1.w) + (v2.w + v3.w);
        }
        for (; j + 2 <= m; j += 2) {
            int c = __shfl_sync(0xffffffffu, idx, j + half);
            float4 v = __ldg(f4 + (size_t)c * 16 + col4);
            acc.x += v.x; acc.y += v.y; acc.z += v.z; acc.w += v.w;
        }
        if (j < m) {
            int c = __shfl_sync(0xffffffffu, idx, m - 1);
            if (half == 0) {
                float4 v = __ldg(f4 + (size_t)c * 16 + col4);
                acc.x += v.x; acc.y += v.y; acc.z += v.z; acc.w += v.w;
            }
        }
    }
    acc.x += __shfl_xor_sync(0xffffffffu, acc.x, 16);
    acc.y += __shfl_xor_sync(0xffffffffu, acc.y, 16);
    acc.z += __shfl_xor_sync(0xffffffffu, acc.z, 16);
    acc.w += __shfl_xor_sync(0xffffffffu, acc.w, 16);
    if (half == 0) {
        float inv = 1.f / (float)max(end - beg, 1);
        acc.x *= inv; acc.y *= inv; acc.z *= inv; acc.w *= inv;
        *(float4*)(agg + (size_t)node * DIM + col4 * 4) = acc;
    }
}

// ---- fused SAGE node update, 2-node register tiling, rotated weight layout ----
__global__ __launch_bounds__(256)
void node_k(const float* __restrict__ xin, const float* __restrict__ agg,
            const float* __restrict__ Wl, const float* __restrict__ bl,
            const float* __restrict__ Wr, float* __restrict__ hout,
            const int* __restrict__ batch, int n_nodes) {
    __shared__ __align__(16) float wlT[DIM * DIM];
    __shared__ __align__(16) float wrT[DIM * DIM];
    __shared__ __align__(16) float ash[32 * DIM];
    __shared__ __align__(16) float xsh[32 * DIM];

    int tid = threadIdx.x;
    for (int i = tid; i < DIM * DIM; i += 256) {
        int o = i >> 6, k = i & 63;
        int rot = (o + 4 * k) & 63;
        wlT[k * DIM + rot] = Wl[i];
        wrT[k * DIM + rot] = Wr[i];
    }
    int q = tid & 15;
    int s = tid >> 4;
    float4 bq = *(const float4*)(bl + 4 * q);

    const float4* agg4 = (const float4*)agg;
    const float4* x4   = (const float4*)xin;
    int base = blockIdx.x * 128;

    for (int r = 0; r < 4; r++) {
        int nb = base + r * 32;
        __syncthreads();
        {
            long long g0 = (long long)nb * 16 + tid;
            long long g1 = g0 + 256;
            long long lim = (long long)n_nodes * 16;
            float4 z = make_float4(0.f, 0.f, 0.f, 0.f);
            ((float4*)ash)[tid]       = (g0 < lim) ? agg4[g0] : z;
            ((float4*)xsh)[tid]       = (g0 < lim) ? x4[g0]   : z;
            ((float4*)ash)[tid + 256] = (g1 < lim) ? agg4[g1] : z;
            ((float4*)xsh)[tid + 256] = (g1 < lim) ? x4[g1]   : z;
        }
        __syncthreads();

        int n0 = nb + s, n1 = nb + s + 16;
        const float* ap0 = &ash[s * DIM];
        const float* xp0 = &xsh[s * DIM];
        const float* ap1 = &ash[(s + 16) * DIM];
        const float* xp1 = &xsh[(s + 16) * DIM];
        unsigned long long a0l0 = 0, a0l1 = 0, a0r0 = 0, a0r1 = 0;
        unsigned long long a1l0 = 0, a1l1 = 0, a1r0 = 0, a1r1 = 0;
#pragma unroll
        for (int k = 0; k < DIM; k++) {
            int rot = (4 * q + 4 * k) & 63;
            unsigned long long av0 = pack2(ap0[k]);
            unsigned long long xv0 = pack2(xp0[k]);
            unsigned long long av1 = pack2(ap1[k]);
            unsigned long long xv1 = pack2(xp1[k]);
            double2 wl = *(const double2*)&wlT[k * DIM + rot];
            double2 wr = *(const double2*)&wrT[k * DIM + rot];
            FMA2(a0l0, av0, __double_as_longlong(wl.x));
            FMA2(a0l1, av0, __double_as_longlong(wl.y));
            FMA2(a0r0, xv0, __double_as_longlong(wr.x));
            FMA2(a0r1, xv0, __double_as_longlong(wr.y));
            FMA2(a1l0, av1, __double_as_longlong(wl.x));
            FMA2(a1l1, av1, __double_as_longlong(wl.y));
            FMA2(a1r0, xv1, __double_as_longlong(wr.x));
            FMA2(a1r1, xv1, __double_as_longlong(wr.y));
        }
#pragma unroll
        for (int nn = 0; nn < 2; nn++) {
            int node = nn ? n1 : n0;
            if (node >= n_nodes) continue;
            float l0, l1, l2, l3, r0, r1, r2, r3;
            if (nn == 0) {
                unpack2(a0l0, l0, l1); unpack2(a0l1, l2, l3);
                unpack2(a0r0, r0, r1); unpack2(a0r1, r2, r3);
            } else {
                unpack2(a1l0, l0, l1); unpack2(a1l1, l2, l3);
                unpack2(a1r0, r0, r1); unpack2(a1r1, r2, r3);
            }
            float4 res;
            res.x = fmaxf(l0 + r0 + bq.x, 0.f);
            res.y = fmaxf(l1 + r1 + bq.y, 0.f);
            res.z = fmaxf(l2 + r2 + bq.z, 0.f);
            res.w = fmaxf(l3 + r3 + bq.w, 0.f);
            if (batch) {
                int g = batch[node];
                red_add_v4(&d_pool[(size_t)g * DIM + 4 * q], res);
            } else {
                *(float4*)&hout[(size_t)node * DIM + 4 * q] = res;
            }
        }
    }
}

// ---- pooled mean -> fc -> log_softmax ----
__global__ void final_k(const float* __restrict__ fcW, const float* __restrict__ fcb,
                        float* __restrict__ out, int G) {
    int g = blockIdx.x * blockDim.x + threadIdx.x;
    if (g >= G) return;
    float inv = 1.f / fmaxf(d_gcnt[g], 1.f);
    float p[DIM];
    const float* pr = &d_pool[(size_t)g * DIM];
#pragma unroll
    for (int k = 0; k < DIM; k++) p[k] = pr[k] * inv;
    float lg[ODIM];
#pragma unroll
    for (int o = 0; o < ODIM; o++) {
        float s = fcb[o];
        const float* w = &fcW[o * DIM];
#pragma unroll
        for (int k = 0; k < DIM; k++) s = fmaf(p[k], w[k], s);
        lg[o] = s;
    }
    float m = lg[0];
#pragma unroll
    for (int o = 1; o < ODIM; o++) m = fmaxf(m, lg[o]);
    float se = 0.f;
#pragma unroll
    for (int o = 0; o < ODIM; o++) se += expf(lg[o] - m);
    float lse = m + logf(se);
#pragma unroll
    for (int o = 0; o < ODIM; o++) out[g * ODIM + o] = lg[o] - lse;
}

extern "C" void kernel_launch(void* const* d_in, const int* in_sizes, int n_in,
                              void* d_out, int out_size) {
    const float* x   = (const float*)d_in[0];
    const float* W1l = (const float*)d_in[1];
    const float* b1  = (const float*)d_in[2];
    const float* W1r = (const float*)d_in[3];
    const float* W2l = (const float*)d_in[4];
    const float* b2  = (const float*)d_in[5];
    const float* W2r = (const float*)d_in[6];
    const float* fcW = (const float*)d_in[7];
    const float* fcb = (const float*)d_in[8];
    const int* ei    = (const int*)d_in[9];     // int32 (JAX x64 disabled)
    const int* batch = (const int*)d_in[10];

    int N = in_sizes[10];
    int E = in_sizes[9] / 2;
    int G = out_size / ODIM;
    int NB = (N + 255) / 256;

    float *agg, *h1;
    cudaGetSymbolAddress((void**)&agg, d_agg);
    cudaGetSymbolAddress((void**)&h1,  d_h1);

    // CSR build; d_deg zero-invariant restored by scan1_k each replay
    count_k<<<(E + 255) / 256, 256>>>(ei, E, batch, N, G);   // 1 (+pool zero, +gcnt)
    scan1_k<<<NB, 256>>>(N);                                 // 2
    scan23_k<<<NB, 256>>>(N, E);                             // 3
    fill_k<<<(E + 255) / 256, 256>>>(ei, E);                 // 4 <- profiled

    // layer 1
    gather_k<<<(N + 7) / 8, 256>>>(x, agg, N);               // 5
    node_k<<<(N + 127) / 128, 256>>>(x, agg, W1l, b1, W1r, h1, nullptr, N);

    // layer 2
    gather_k<<<(N + 7) / 8, 256>>>(h1, agg, N);
    node_k<<<(N + 127) / 128, 256>>>(h1, agg, W2l, b2, W2r, nullptr, batch, N);

    // pool -> fc -> log_softmax
    final_k<<<(G + 255) / 256, 256>>>(fcW, fcb, (float*)d_out, G);
}

// round 9
// speedup vs baseline: 1.5691x; 1.2978x over previous
#include <cuda_runtime.h>
#include <cstdint>

#define DIM   64
#define ODIM  16
#define NMAX  100000
#define EMAX  1600000
#define GMAX  512
#define NB_SCAN 512

// ---- scratch (no allocations allowed; __device__ globals per rules) ----
// INVARIANT: d_deg all-zero at kernel_launch entry (zero at module load;
// scan1_k re-zeroes after reading, so every replay restores the invariant).
__device__ __align__(16) float d_agg[(size_t)NMAX * DIM];
__device__ __align__(16) float d_h1 [(size_t)NMAX * DIM];
__device__ __align__(16) float d_pool[(size_t)GMAX * DIM];
__device__ float d_gcnt[GMAX];
__device__ int d_deg[NMAX];
__device__ int d_off[NMAX + 1];
__device__ int d_cur[NMAX];
__device__ int d_col[EMAX];
__device__ int d_bsum[NB_SCAN];

// ---- helpers ----
__device__ __forceinline__ void red_add_v4(float* p, float4 v) {
    asm volatile("red.global.add.v4.f32 [%0], {%1,%2,%3,%4};"
                 :: "l"(p), "f"(v.x), "f"(v.y), "f"(v.z), "f"(v.w) : "memory");
}
__device__ __forceinline__ unsigned long long pack2(float v) {
    unsigned long long r;
    asm("mov.b64 %0, {%1,%1};" : "=l"(r) : "r"(__float_as_uint(v)));
    return r;
}
__device__ __forceinline__ void unpack2(unsigned long long v, float& lo, float& hi) {
    unsigned int a, b;
    asm("mov.b64 {%0,%1}, %2;" : "=r"(a), "=r"(b) : "l"(v));
    lo = __uint_as_float(a); hi = __uint_as_float(b);
}
#define FMA2(acc, a, b) \
    asm("fma.rn.f32x2 %0, %1, %2, %0;" : "+l"(acc) : "l"(a), "l"(b))

// ---- launch 1: degree count + (piggyback) pool zero + group counts ----
__global__ void count_k(const int* __restrict__ ei, int E,
                        const int* __restrict__ batch, int n, int G) {
    int b = blockIdx.x;
    int tid = threadIdx.x;
    int e = b * 256 + tid;
    if (e < E) atomicAdd(&d_deg[__ldg(&ei[E + e])], 1);
    if (b < 128) {
        int i = b * 256 + tid;
        if (i < G * DIM) d_pool[i] = 0.f;
    } else if (b < 130) {
        int g = (b - 128) * 256 + tid;
        if (g < G) {
            int lo = 0, hi = n;
            while (lo < hi) { int m = (lo + hi) >> 1; if (batch[m] < g) lo = m + 1; else hi = m; }
            int lo2 = lo, hi2 = n;
            while (lo2 < hi2) { int m = (lo2 + hi2) >> 1; if (batch[m] < g + 1) lo2 = m + 1; else hi2 = m; }
            d_gcnt[g] = (float)(lo2 - lo);
        }
    }
}

// ---- launch 2: per-block exclusive scan; re-zero deg (replay invariant) ----
__global__ void scan1_k(int n) {
    __shared__ int sh[256];
    int tid = threadIdx.x;
    int i = blockIdx.x * 256 + tid;
    int v = 0;
    if (i < n) { v = d_deg[i]; d_deg[i] = 0; }
    sh[tid] = v;
    __syncthreads();
#pragma unroll
    for (int o = 1; o < 256; o <<= 1) {
        int t = (tid >= o) ? sh[tid - o] : 0;
        __syncthreads();
        if (tid >= o) sh[tid] += t;
        __syncthreads();
    }
    if (i < n) d_off[i] = sh[tid] - v;
    if (tid == 255) d_bsum[blockIdx.x] = sh[255];
}
// ---- launch 3: fused level-2+3 ----
__global__ void scan23_k(int n, int E) {
    __shared__ int red[8];
    __shared__ int sprev;
    int b = blockIdx.x;
    int tid = threadIdx.x;
    int s = 0;
    for (int j = tid; j < b; j += 256) s += d_bsum[j];
#pragma unroll
    for (int o = 16; o; o >>= 1) s += __shfl_xor_sync(0xffffffffu, s, o);
    if ((tid & 31) == 0) red[tid >> 5] = s;
    __syncthreads();
    if (tid == 0) {
        int t = 0;
#pragma unroll
        for (int w = 0; w < 8; w++) t += red[w];
        sprev = t;
    }
    __syncthreads();
    int i = b * 256 + tid;
    if (i < n) {
        int o = d_off[i] + sprev;
        d_off[i] = o;
        d_cur[i] = o;
    }
    if (b == 0 && tid == 0) d_off[n] = E;
}

// ---- launch 4: CSR fill ----
__global__ void fill_k(const int* __restrict__ ei, int E) {
    int e = blockIdx.x * blockDim.x + threadIdx.x;
    if (e >= E) return;
    int s = __ldg(&ei[e]);
    int d = __ldg(&ei[E + e]);
    int p = atomicAdd(&d_cur[d], 1);
    d_col[p] = s;
}

// ---- gather: warp per node; idx coalesced + shfl-broadcast; 8-edge batches
//      (R7-measured best: 45.4us; 16-edge variant regressed via reg pressure) ----
__global__ __launch_bounds__(256)
void gather_k(const float* __restrict__ feat, float* __restrict__ agg, int N) {
    int node = (blockIdx.x * 256 + threadIdx.x) >> 5;
    int lane = threadIdx.x & 31;
    if (node >= N) return;
    int beg = d_off[node];
    int end = d_off[node + 1];
    int half = lane >> 4;
    int col4 = lane & 15;
    const float4* f4 = (const float4*)feat;
    float4 acc = make_float4(0.f, 0.f, 0.f, 0.f);
    for (int b = beg; b < end; b += 32) {
        int m = min(32, end - b);
        int idx = (lane < m) ? __ldg(&d_col[b + lane]) : 0;
        int j = 0;
        for (; j + 8 <= m; j += 8) {
            int c0 = __shfl_sync(0xffffffffu, idx, j     + half);
            int c1 = __shfl_sync(0xffffffffu, idx, j + 2 + half);
            int c2 = __shfl_sync(0xffffffffu, idx, j + 4 + half);
            int c3 = __shfl_sync(0xffffffffu, idx, j + 6 + half);
            float4 v0 = __ldg(f4 + (size_t)c0 * 16 + col4);
            float4 v1 = __ldg(f4 + (size_t)c1 * 16 + col4);
            float4 v2 = __ldg(f4 + (size_t)c2 * 16 + col4);
            float4 v3 = __ldg(f4 + (size_t)c3 * 16 + col4);
            acc.x += (v0.x + v1.x) + (v2.x + v3.x);
            acc.y += (v0.y + v1.y) + (v2.y + v3.y);
            acc.z += (v0.z + v1.z) + (v2.z + v3.z);
            acc.w += (v0.w + v1.w) + (v2.w + v3.w);
        }
        for (; j + 2 <= m; j += 2) {
            int c = __shfl_sync(0xffffffffu, idx, j + half);
            float4 v = __ldg(f4 + (size_t)c * 16 + col4);
            acc.x += v.x; acc.y += v.y; acc.z += v.z; acc.w += v.w;
        }
        if (j < m) {
            int c = __shfl_sync(0xffffffffu, idx, m - 1);
            if (half == 0) {
                float4 v = __ldg(f4 + (size_t)c * 16 + col4);
                acc.x += v.x; acc.y += v.y; acc.z += v.z; acc.w += v.w;
            }
        }
    }
    acc.x += __shfl_xor_sync(0xffffffffu, acc.x, 16);
    acc.y += __shfl_xor_sync(0xffffffffu, acc.y, 16);
    acc.z += __shfl_xor_sync(0xffffffffu, acc.z, 16);
    acc.w += __shfl_xor_sync(0xffffffffu, acc.w, 16);
    if (half == 0) {
        float inv = 1.f / (float)max(end - beg, 1);
        acc.x *= inv; acc.y *= inv; acc.z *= inv; acc.w *= inv;
        *(float4*)(agg + (size_t)node * DIM + col4 * 4) = acc;
    }
}

// ---- fused SAGE node update, 4-node register tiling, 64KB dynamic smem ----
// Each weight double2 LDS feeds 4 nodes (16 FMA2/k); a/x values loaded as
// float4 per 4 k. Weight rows rotated by 4k so the 16 q-lanes hit 16 distinct
// 16B banks regardless of k (conflict-free LDS.128).
__global__ __launch_bounds__(256)
void node_k(const float* __restrict__ xin, const float* __restrict__ agg,
            const float* __restrict__ Wl, const float* __restrict__ bl,
            const float* __restrict__ Wr, float* __restrict__ hout,
            const int* __restrict__ batch, int n_nodes) {
    extern __shared__ __align__(16) float smem[];
    float* wlT = smem;                 // 4096 floats
    float* wrT = smem + 4096;          // 4096
    float* ash = smem + 8192;          // 64 rows x 64
    float* xsh = smem + 12288;         // 64 rows x 64

    int tid = threadIdx.x;
    for (int i = tid; i < DIM * DIM; i += 256) {
        int o = i >> 6, k = i & 63;
        int rot = (o + 4 * k) & 63;
        wlT[k * DIM + rot] = Wl[i];
        wrT[k * DIM + rot] = Wr[i];
    }
    {   // stage 64 node rows of agg and x (16KB each, coalesced)
        int nb = blockIdx.x * 64;
        long long base4 = (long long)nb * 16;
        long long lim = (long long)n_nodes * 16;
        const float4* agg4 = (const float4*)agg;
        const float4* x4   = (const float4*)xin;
        float4 z = make_float4(0.f, 0.f, 0.f, 0.f);
#pragma unroll
        for (int t = 0; t < 4; t++) {
            int i = tid + t * 256;
            long long g = base4 + i;
            ((float4*)ash)[i] = (g < lim) ? agg4[g] : z;
            ((float4*)xsh)[i] = (g < lim) ? x4[g]   : z;
        }
    }
    __syncthreads();

    int q = tid & 15;
    int s = tid >> 4;
    float4 bq = *(const float4*)(bl + 4 * q);

    unsigned long long accl[4][2] = {{0,0},{0,0},{0,0},{0,0}};
    unsigned long long accr[4][2] = {{0,0},{0,0},{0,0},{0,0}};

#pragma unroll 4
    for (int k0 = 0; k0 < DIM; k0 += 4) {
        float av[4][4], xv[4][4];
#pragma unroll
        for (int j = 0; j < 4; j++) {
            *(float4*)av[j] = *(const float4*)&ash[(s + 16 * j) * DIM + k0];
            *(float4*)xv[j] = *(const float4*)&xsh[(s + 16 * j) * DIM + k0];
        }
#pragma unroll
        for (int kk = 0; kk < 4; kk++) {
            int k = k0 + kk;
            int rot = (4 * q + 4 * k) & 63;
            double2 wl = *(const double2*)&wlT[k * DIM + rot];
            double2 wr = *(const double2*)&wrT[k * DIM + rot];
            unsigned long long wlx = __double_as_longlong(wl.x);
            unsigned long long wly = __double_as_longlong(wl.y);
            unsigned long long wrx = __double_as_longlong(wr.x);
            unsigned long long wry = __double_as_longlong(wr.y);
#pragma unroll
            for (int j = 0; j < 4; j++) {
                unsigned long long a2 = pack2(av[j][kk]);
                unsigned long long x2 = pack2(xv[j][kk]);
                FMA2(accl[j][0], a2, wlx);
                FMA2(accl[j][1], a2, wly);
                FMA2(accr[j][0], x2, wrx);
                FMA2(accr[j][1], x2, wry);
            }
        }
    }

    int nb = blockIdx.x * 64;
#pragma unroll
    for (int j = 0; j < 4; j++) {
        int node = nb + s + 16 * j;
        if (node >= n_nodes) continue;
        float l0, l1, l2, l3, r0, r1, r2, r3;
        unpack2(accl[j][0], l0, l1); unpack2(accl[j][1], l2, l3);
        unpack2(accr[j][0], r0, r1); unpack2(accr[j][1], r2, r3);
        float4 res;
        res.x = fmaxf(l0 + r0 + bq.x, 0.f);
        res.y = fmaxf(l1 + r1 + bq.y, 0.f);
        res.z = fmaxf(l2 + r2 + bq.z, 0.f);
        res.w = fmaxf(l3 + r3 + bq.w, 0.f);
        if (batch) {
            int g = batch[node];
            red_add_v4(&d_pool[(size_t)g * DIM + 4 * q], res);
        } else {
            *(float4*)&hout[(size_t)node * DIM + 4 * q] = res;
        }
    }
}
#define NODE_SMEM (16384 * 4)

// ---- pooled mean -> fc -> log_softmax ----
__global__ void final_k(const float* __restrict__ fcW, const float* __restrict__ fcb,
                        float* __restrict__ out, int G) {
    int g = blockIdx.x * blockDim.x + threadIdx.x;
    if (g >= G) return;
    float inv = 1.f / fmaxf(d_gcnt[g], 1.f);
    float p[DIM];
    const float* pr = &d_pool[(size_t)g * DIM];
#pragma unroll
    for (int k = 0; k < DIM; k++) p[k] = pr[k] * inv;
    float lg[ODIM];
#pragma unroll
    for (int o = 0; o < ODIM; o++) {
        float s = fcb[o];
        const float* w = &fcW[o * DIM];
#pragma unroll
        for (int k = 0; k < DIM; k++) s = fmaf(p[k], w[k], s);
        lg[o] = s;
    }
    float m = lg[0];
#pragma unroll
    for (int o = 1; o < ODIM; o++) m = fmaxf(m, lg[o]);
    float se = 0.f;
#pragma unroll
    for (int o = 0; o < ODIM; o++) se += expf(lg[o] - m);
    float lse = m + logf(se);
#pragma unroll
    for (int o = 0; o < ODIM; o++) out[g * ODIM + o] = lg[o] - lse;
}

extern "C" void kernel_launch(void* const* d_in, const int* in_sizes, int n_in,
                              void* d_out, int out_size) {
    const float* x   = (const float*)d_in[0];
    const float* W1l = (const float*)d_in[1];
    const float* b1  = (const float*)d_in[2];
    const float* W1r = (const float*)d_in[3];
    const float* W2l = (const float*)d_in[4];
    const float* b2  = (const float*)d_in[5];
    const float* W2r = (const float*)d_in[6];
    const float* fcW = (const float*)d_in[7];
    const float* fcb = (const float*)d_in[8];
    const int* ei    = (const int*)d_in[9];     // int32 (JAX x64 disabled)
    const int* batch = (const int*)d_in[10];

    int N = in_sizes[10];
    int E = in_sizes[9] / 2;
    int G = out_size / ODIM;
    int NB = (N + 255) / 256;

    float *agg, *h1;
    cudaGetSymbolAddress((void**)&agg, d_agg);
    cudaGetSymbolAddress((void**)&h1,  d_h1);

    static int smem_set = 0;   // attribute is sticky; set once (host-side, not a graph op)
    if (!smem_set) {
        cudaFuncSetAttribute(node_k, cudaFuncAttributeMaxDynamicSharedMemorySize, NODE_SMEM);
        smem_set = 1;
    }

    // CSR build; d_deg zero-invariant restored by scan1_k each replay
    count_k<<<(E + 255) / 256, 256>>>(ei, E, batch, N, G);
    scan1_k<<<NB, 256>>>(N);
    scan23_k<<<NB, 256>>>(N, E);
    fill_k<<<(E + 255) / 256, 256>>>(ei, E);

    // layer 1
    gather_k<<<(N + 7) / 8, 256>>>(x, agg, N);
    node_k<<<(N + 63) / 64, 256, NODE_SMEM>>>(x, agg, W1l, b1, W1r, h1, nullptr, N);

    // layer 2
    gather_k<<<(N + 7) / 8, 256>>>(h1, agg, N);
    node_k<<<(N + 63) / 64, 256, NODE_SMEM>>>(h1, agg, W2l, b2, W2r, nullptr, batch, N);

    // pool -> fc -> log_softmax
    final_k<<<(G + 255) / 256, 256>>>(fcW, fcb, (float*)d_out, G);
}